// round 6
// baseline (speedup 1.0000x reference)
#include <cuda_runtime.h>

#define B 8
#define S 64
#define V 50257
#define P 200
#define WORDS 1571            // ceil(V/32)
#define NCHUNK 8
#define CV 6284               // NCHUNK*CV >= V
#define THREADS 512
#define INV_T  (1.0f/0.6f)
#define PEN    1.2f
#define INV_PEN (1.0f/1.2f)

__device__ unsigned int g_mask[S * WORDS];
__device__ float g_pm[S * NCHUNK * B];
__device__ float g_pl[S * NCHUNK * B];
__device__ float g_M[S * B];
__device__ float g_R[S * B];

__global__ void k_clear() {
    int i = blockIdx.x * blockDim.x + threadIdx.x;
    if (i < S * WORDS) g_mask[i] = 0u;
}

// prev_tokens arrives as int32 (JAX default config downgrades the int64 request).
__global__ void k_scatter(const int* __restrict__ prev) {
    int i = blockIdx.x * blockDim.x + threadIdx.x;
    if (i < S * P) {
        int s = i / P;
        int t = prev[i];
        atomicOr(&g_mask[s * WORDS + (t >> 5)], 1u << (t & 31));
    }
}

// Pass A: per (s, v-chunk) CTA, online softmax stats for all 8 batch rows.
__global__ __launch_bounds__(THREADS) void k_passA(const float* __restrict__ logits) {
    const int c = blockIdx.x & (NCHUNK - 1);
    const int s = blockIdx.x >> 3;
    const int v0 = c * CV;
    const int v1 = min(v0 + CV, V);
    const float* base = logits + (size_t)s * V;
    const unsigned int* mrow = g_mask + s * WORDS;
    const size_t bstride = (size_t)S * V;

    float m[B], l[B];
#pragma unroll
    for (int b = 0; b < B; b++) { m[b] = -1e30f; l[b] = 0.0f; }

    for (int v = v0 + threadIdx.x; v < v1; v += THREADS) {
        const unsigned int bit = (mrow[v >> 5] >> (v & 31)) & 1u;
        float x[B];
        bool allneg = true;
#pragma unroll
        for (int b = 0; b < B; b++) {
            x[b] = base[(size_t)b * bstride + v];
            allneg = allneg && (x[b] < 0.0f);
        }
        const float fac = bit ? (allneg ? PEN : INV_PEN) : 1.0f;
#pragma unroll
        for (int b = 0; b < B; b++) {
            const float xs = x[b] * fac * INV_T;
            if (xs > m[b]) {
                l[b] = l[b] * __expf(m[b] - xs) + 1.0f;
                m[b] = xs;
            } else {
                l[b] += __expf(xs - m[b]);
            }
        }
    }

    // warp reduce (combine (m,l) pairs)
#pragma unroll
    for (int b = 0; b < B; b++) {
#pragma unroll
        for (int off = 16; off; off >>= 1) {
            const float om = __shfl_xor_sync(0xffffffffu, m[b], off);
            const float ol = __shfl_xor_sync(0xffffffffu, l[b], off);
            const float nm = fmaxf(m[b], om);
            l[b] = l[b] * __expf(m[b] - nm) + ol * __expf(om - nm);
            m[b] = nm;
        }
    }

    __shared__ float sm[THREADS / 32][B];
    __shared__ float sl[THREADS / 32][B];
    const int warp = threadIdx.x >> 5;
    const int lane = threadIdx.x & 31;
    if (lane == 0) {
#pragma unroll
        for (int b = 0; b < B; b++) { sm[warp][b] = m[b]; sl[warp][b] = l[b]; }
    }
    __syncthreads();
    if (threadIdx.x < B) {
        const int b = threadIdx.x;
        float M = sm[0][b], L = sl[0][b];
#pragma unroll
        for (int w = 1; w < THREADS / 32; w++) {
            const float om = sm[w][b], ol = sl[w][b];
            const float nm = fmaxf(M, om);
            L = L * __expf(M - nm) + ol * __expf(om - nm);
            M = nm;
        }
        g_pm[(s * NCHUNK + c) * B + b] = M;
        g_pl[(s * NCHUNK + c) * B + b] = L;
    }
}

__global__ void k_reduce() {
    const int i = threadIdx.x;          // S*B = 512 threads
    if (i < S * B) {
        const int s = i / B;
        const int b = i % B;
        float M = -1e30f, L = 0.0f;
#pragma unroll
        for (int c = 0; c < NCHUNK; c++) {
            const float om = g_pm[(s * NCHUNK + c) * B + b];
            const float ol = g_pl[(s * NCHUNK + c) * B + b];
            const float nm = fmaxf(M, om);
            L = L * __expf(M - nm) + ol * __expf(om - nm);
            M = nm;
        }
        g_M[s * B + b] = M;
        g_R[s * B + b] = 1.0f / L;
    }
}

// Pass C: recompute penalized value, normalize, write.
__global__ __launch_bounds__(THREADS) void k_passC(const float* __restrict__ logits,
                                                   float* __restrict__ out) {
    const int c = blockIdx.x & (NCHUNK - 1);
    const int s = blockIdx.x >> 3;
    const int v0 = c * CV;
    const int v1 = min(v0 + CV, V);
    const float* base = logits + (size_t)s * V;
    float* obase = out + (size_t)s * V;
    const unsigned int* mrow = g_mask + s * WORDS;
    const size_t bstride = (size_t)S * V;

    float M[B], R[B];
#pragma unroll
    for (int b = 0; b < B; b++) {
        M[b] = g_M[s * B + b];
        R[b] = g_R[s * B + b];
    }

    for (int v = v0 + threadIdx.x; v < v1; v += THREADS) {
        const unsigned int bit = (mrow[v >> 5] >> (v & 31)) & 1u;
        float x[B];
        bool allneg = true;
#pragma unroll
        for (int b = 0; b < B; b++) {
            x[b] = base[(size_t)b * bstride + v];
            allneg = allneg && (x[b] < 0.0f);
        }
        const float fac = bit ? (allneg ? PEN : INV_PEN) : 1.0f;
#pragma unroll
        for (int b = 0; b < B; b++) {
            const float xs = x[b] * fac * INV_T;
            obase[(size_t)b * bstride + v] = __expf(xs - M[b]) * R[b];
        }
    }
}

extern "C" void kernel_launch(void* const* d_in, const int* in_sizes, int n_in,
                              void* d_out, int out_size) {
    const float* logits = (const float*)d_in[0];
    const int* prev = (const int*)d_in[1];
    float* out = (float*)d_out;
    (void)in_sizes; (void)n_in; (void)out_size;

    k_clear<<<(S * WORDS + 255) / 256, 256>>>();
    k_scatter<<<(S * P + 255) / 256, 256>>>(prev);
    k_passA<<<S * NCHUNK, THREADS>>>(logits);
    k_reduce<<<1, S * B>>>();
    k_passC<<<S * NCHUNK, THREADS>>>(logits, out);
}

// round 7
// speedup vs baseline: 1.4990x; 1.4990x over previous
#include <cuda_runtime.h>

#define B 8
#define S 64
#define V 50257
#define P 200
#define NCHUNK 13
#define CV 3866               // NCHUNK*CV = 50258 >= V
#define MWORDS 121            // ceil(CV/32)
#define THREADS 256
#define INV_T  (1.0f/0.6f)
#define PEN    1.2f
#define INV_PEN (1.0f/1.2f)

__device__ float g_pl[S * NCHUNK * B];   // partial sums of exp(xs)

// Build the penalty bitmask for this CTA's v-range in shared memory.
__device__ __forceinline__ void build_mask(unsigned* smask, const int* __restrict__ prev,
                                           int s, int v0, int v1) {
    for (int i = threadIdx.x; i < MWORDS; i += THREADS) smask[i] = 0u;
    __syncthreads();
    for (int t = threadIdx.x; t < P; t += THREADS) {
        const int tok = prev[s * P + t];
        if (tok >= v0 && tok < v1) {
            const int r = tok - v0;
            atomicOr(&smask[r >> 5], 1u << (r & 31));
        }
    }
}

// Pass A: per (s, v-chunk) CTA: sum of exp(penalized * 1/T) for all 8 batch rows.
__global__ __launch_bounds__(THREADS) void k_passA(const float* __restrict__ logits,
                                                   const int* __restrict__ prev) {
    const int c = blockIdx.x % NCHUNK;
    const int s = blockIdx.x / NCHUNK;
    const int v0 = c * CV;
    const int v1 = min(v0 + CV, V);

    __shared__ unsigned smask[MWORDS];
    build_mask(smask, prev, s, v0, v1);
    __syncthreads();

    const float* base = logits + (size_t)s * V;
    const size_t bstride = (size_t)S * V;

    float sum[B];
#pragma unroll
    for (int b = 0; b < B; b++) sum[b] = 0.0f;

    for (int v = v0 + threadIdx.x; v < v1; v += THREADS) {
        const int r = v - v0;
        const unsigned bit = (smask[r >> 5] >> (r & 31)) & 1u;
        float x[B];
        bool allneg = true;
#pragma unroll
        for (int b = 0; b < B; b++) {
            x[b] = base[(size_t)b * bstride + v];
            allneg = allneg && (x[b] < 0.0f);
        }
        const float fac = (bit ? (allneg ? PEN : INV_PEN) : 1.0f) * INV_T;
#pragma unroll
        for (int b = 0; b < B; b++)
            sum[b] += __expf(x[b] * fac);
    }

    // warp add-reduce
#pragma unroll
    for (int b = 0; b < B; b++) {
#pragma unroll
        for (int off = 16; off; off >>= 1)
            sum[b] += __shfl_xor_sync(0xffffffffu, sum[b], off);
    }

    __shared__ float ssum[THREADS / 32][B];
    const int warp = threadIdx.x >> 5;
    const int lane = threadIdx.x & 31;
    if (lane == 0) {
#pragma unroll
        for (int b = 0; b < B; b++) ssum[warp][b] = sum[b];
    }
    __syncthreads();
    if (threadIdx.x < B) {
        const int b = threadIdx.x;
        float L = 0.0f;
#pragma unroll
        for (int w = 0; w < THREADS / 32; w++) L += ssum[w][b];
        g_pl[(s * NCHUNK + c) * B + b] = L;
    }
}

// Pass C: inline chunk-reduce, recompute penalized exp, normalize, write.
__global__ __launch_bounds__(THREADS) void k_passC(const float* __restrict__ logits,
                                                   const int* __restrict__ prev,
                                                   float* __restrict__ out) {
    const int c = blockIdx.x % NCHUNK;
    const int s = blockIdx.x / NCHUNK;
    const int v0 = c * CV;
    const int v1 = min(v0 + CV, V);

    __shared__ unsigned smask[MWORDS];
    __shared__ float sR[B];
    build_mask(smask, prev, s, v0, v1);
    if (threadIdx.x < B) {
        float L = 0.0f;
#pragma unroll
        for (int cc = 0; cc < NCHUNK; cc++)
            L += g_pl[(s * NCHUNK + cc) * B + threadIdx.x];
        sR[threadIdx.x] = 1.0f / L;
    }
    __syncthreads();

    float R[B];
#pragma unroll
    for (int b = 0; b < B; b++) R[b] = sR[b];

    const float* base = logits + (size_t)s * V;
    float* obase = out + (size_t)s * V;
    const size_t bstride = (size_t)S * V;

    for (int v = v0 + threadIdx.x; v < v1; v += THREADS) {
        const int r = v - v0;
        const unsigned bit = (smask[r >> 5] >> (r & 31)) & 1u;
        float x[B];
        bool allneg = true;
#pragma unroll
        for (int b = 0; b < B; b++) {
            x[b] = base[(size_t)b * bstride + v];
            allneg = allneg && (x[b] < 0.0f);
        }
        const float fac = (bit ? (allneg ? PEN : INV_PEN) : 1.0f) * INV_T;
#pragma unroll
        for (int b = 0; b < B; b++)
            obase[(size_t)b * bstride + v] = __expf(x[b] * fac) * R[b];
    }
}

extern "C" void kernel_launch(void* const* d_in, const int* in_sizes, int n_in,
                              void* d_out, int out_size) {
    const float* logits = (const float*)d_in[0];
    const int* prev = (const int*)d_in[1];
    float* out = (float*)d_out;
    (void)in_sizes; (void)n_in; (void)out_size;

    k_passA<<<S * NCHUNK, THREADS>>>(logits, prev);
    k_passC<<<S * NCHUNK, THREADS>>>(logits, prev, out);
}

// round 8
// speedup vs baseline: 1.6584x; 1.1063x over previous
#include <cuda_runtime.h>

#define B 8
#define S 64
#define V 50257
#define P 200
#define NCHUNK 9
#define THREADS 256
#define MWORDS 180            // covers max chunk span (<=5584 floats -> 175 words) + pad
#define INV_T  (1.0f/0.6f)
#define PEN    1.2f
#define INV_PEN (1.0f/1.2f)
#define BSTRIDE  ((size_t)S * V)       // 3216448 (divisible by 4)
#define BSTRIDE4 (BSTRIDE / 4)

__device__ float g_pl[S * NCHUNK * B];

// Compute this CTA's aligned vector range for sequence s, chunk c.
__device__ __forceinline__ void chunk_range(int s, int c, int& a, int& G, int& v0, int& v1) {
    a = (4 - (s & 3)) & 3;               // first v with (s*V + v) % 4 == 0
    G = (V - a) >> 2;                    // total float4 groups for this s
    const int g0 = (int)(((long long)c * G) / NCHUNK);
    const int g1 = (int)(((long long)(c + 1) * G) / NCHUNK);
    v0 = a + 4 * g0;
    v1 = a + 4 * g1;
}

__device__ __forceinline__ void build_mask(unsigned* smask, int* sprev,
                                           const int* __restrict__ prev,
                                           int s, int v0, int v1) {
    for (int i = threadIdx.x; i < MWORDS; i += THREADS) smask[i] = 0u;
    __syncthreads();
    for (int t = threadIdx.x; t < P; t += THREADS) {
        const int tok = prev[s * P + t];
        sprev[t] = tok;
        if (tok >= v0 && tok < v1) {
            const int r = tok - v0;
            atomicOr(&smask[r >> 5], 1u << (r & 31));
        }
    }
}

// Pass A: partial sums of exp(penalized * 1/T) per (s, chunk, b).
__global__ __launch_bounds__(THREADS, 4) void k_passA(const float* __restrict__ logits,
                                                      const int* __restrict__ prev) {
    const int c = blockIdx.x % NCHUNK;
    const int s = blockIdx.x / NCHUNK;
    int a, G, v0, v1;
    chunk_range(s, c, a, G, v0, v1);

    __shared__ unsigned smask[MWORDS];
    __shared__ int sprev[P];
    build_mask(smask, sprev, prev, s, v0, v1);
    __syncthreads();

    const float* base = logits + (size_t)s * V;
    float sum[B];
#pragma unroll
    for (int b = 0; b < B; b++) sum[b] = 0.0f;

    for (int v = v0 + 4 * threadIdx.x; v < v1; v += 4 * THREADS) {
        const int r = v - v0;                         // multiple of 4 -> no word straddle
        const unsigned bits4 = (smask[r >> 5] >> (r & 31)) & 0xFu;
        const float4* p = (const float4*)(base + v);
        float4 x[B];
#pragma unroll
        for (int b = 0; b < B; b++) x[b] = p[(size_t)b * BSTRIDE4];
        float4 mx = x[0];
#pragma unroll
        for (int b = 1; b < B; b++) {
            mx.x = fmaxf(mx.x, x[b].x); mx.y = fmaxf(mx.y, x[b].y);
            mx.z = fmaxf(mx.z, x[b].z); mx.w = fmaxf(mx.w, x[b].w);
        }
        float fac[4];
        fac[0] = ((bits4 & 1u) ? (mx.x < 0.0f ? PEN : INV_PEN) : 1.0f) * INV_T;
        fac[1] = ((bits4 & 2u) ? (mx.y < 0.0f ? PEN : INV_PEN) : 1.0f) * INV_T;
        fac[2] = ((bits4 & 4u) ? (mx.z < 0.0f ? PEN : INV_PEN) : 1.0f) * INV_T;
        fac[3] = ((bits4 & 8u) ? (mx.w < 0.0f ? PEN : INV_PEN) : 1.0f) * INV_T;
#pragma unroll
        for (int b = 0; b < B; b++)
            sum[b] += __expf(x[b].x * fac[0]) + __expf(x[b].y * fac[1])
                    + __expf(x[b].z * fac[2]) + __expf(x[b].w * fac[3]);
    }

    // chunk 0 handles the <=6 unaligned scalar elements (head [0,a), tail [a+4G, V))
    if (c == 0) {
        const int tail0 = a + 4 * G;
        const int cnt = a + (V - tail0);
        if ((int)threadIdx.x < cnt) {
            const int v = ((int)threadIdx.x < a) ? (int)threadIdx.x
                                                 : tail0 + ((int)threadIdx.x - a);
            bool hit = false;
            for (int t = 0; t < P; t++) hit |= (sprev[t] == v);
            float x[B];
            bool allneg = true;
#pragma unroll
            for (int b = 0; b < B; b++) {
                x[b] = base[(size_t)b * BSTRIDE + v];
                allneg = allneg && (x[b] < 0.0f);
            }
            const float fac = (hit ? (allneg ? PEN : INV_PEN) : 1.0f) * INV_T;
#pragma unroll
            for (int b = 0; b < B; b++) sum[b] += __expf(x[b] * fac);
        }
    }

    // block reduce
#pragma unroll
    for (int b = 0; b < B; b++) {
#pragma unroll
        for (int off = 16; off; off >>= 1)
            sum[b] += __shfl_xor_sync(0xffffffffu, sum[b], off);
    }
    __shared__ float ssum[THREADS / 32][B];
    const int warp = threadIdx.x >> 5;
    const int lane = threadIdx.x & 31;
    if (lane == 0) {
#pragma unroll
        for (int b = 0; b < B; b++) ssum[warp][b] = sum[b];
    }
    __syncthreads();
    if (threadIdx.x < B) {
        const int b = threadIdx.x;
        float L = 0.0f;
#pragma unroll
        for (int w = 0; w < THREADS / 32; w++) L += ssum[w][b];
        g_pl[(s * NCHUNK + c) * B + b] = L;
    }
}

// Pass C: inline reduce of partials, recompute penalized exp, normalize, write.
__global__ __launch_bounds__(THREADS, 4) void k_passC(const float* __restrict__ logits,
                                                      const int* __restrict__ prev,
                                                      float* __restrict__ out) {
    const int c = blockIdx.x % NCHUNK;
    const int s = blockIdx.x / NCHUNK;
    int a, G, v0, v1;
    chunk_range(s, c, a, G, v0, v1);

    __shared__ unsigned smask[MWORDS];
    __shared__ int sprev[P];
    __shared__ float sR[B];
    build_mask(smask, sprev, prev, s, v0, v1);
    if (threadIdx.x < B) {
        float L = 0.0f;
#pragma unroll
        for (int cc = 0; cc < NCHUNK; cc++)
            L += g_pl[(s * NCHUNK + cc) * B + threadIdx.x];
        sR[threadIdx.x] = 1.0f / L;
    }
    __syncthreads();

    float R[B];
#pragma unroll
    for (int b = 0; b < B; b++) R[b] = sR[b];

    const float* base = logits + (size_t)s * V;
    float* obase = out + (size_t)s * V;

    for (int v = v0 + 4 * threadIdx.x; v < v1; v += 4 * THREADS) {
        const int r = v - v0;
        const unsigned bits4 = (smask[r >> 5] >> (r & 31)) & 0xFu;
        const float4* p = (const float4*)(base + v);
        float4* q = (float4*)(obase + v);
        float4 x[B];
#pragma unroll
        for (int b = 0; b < B; b++) x[b] = p[(size_t)b * BSTRIDE4];
        float4 mx = x[0];
#pragma unroll
        for (int b = 1; b < B; b++) {
            mx.x = fmaxf(mx.x, x[b].x); mx.y = fmaxf(mx.y, x[b].y);
            mx.z = fmaxf(mx.z, x[b].z); mx.w = fmaxf(mx.w, x[b].w);
        }
        float fac[4];
        fac[0] = ((bits4 & 1u) ? (mx.x < 0.0f ? PEN : INV_PEN) : 1.0f) * INV_T;
        fac[1] = ((bits4 & 2u) ? (mx.y < 0.0f ? PEN : INV_PEN) : 1.0f) * INV_T;
        fac[2] = ((bits4 & 4u) ? (mx.z < 0.0f ? PEN : INV_PEN) : 1.0f) * INV_T;
        fac[3] = ((bits4 & 8u) ? (mx.w < 0.0f ? PEN : INV_PEN) : 1.0f) * INV_T;
#pragma unroll
        for (int b = 0; b < B; b++) {
            float4 o;
            o.x = __expf(x[b].x * fac[0]) * R[b];
            o.y = __expf(x[b].y * fac[1]) * R[b];
            o.z = __expf(x[b].z * fac[2]) * R[b];
            o.w = __expf(x[b].w * fac[3]) * R[b];
            q[(size_t)b * BSTRIDE4] = o;
        }
    }

    if (c == 0) {
        const int tail0 = a + 4 * G;
        const int cnt = a + (V - tail0);
        if ((int)threadIdx.x < cnt) {
            const int v = ((int)threadIdx.x < a) ? (int)threadIdx.x
                                                 : tail0 + ((int)threadIdx.x - a);
            bool hit = false;
            for (int t = 0; t < P; t++) hit |= (sprev[t] == v);
            float x[B];
            bool allneg = true;
#pragma unroll
            for (int b = 0; b < B; b++) {
                x[b] = base[(size_t)b * BSTRIDE + v];
                allneg = allneg && (x[b] < 0.0f);
            }
            const float fac = (hit ? (allneg ? PEN : INV_PEN) : 1.0f) * INV_T;
#pragma unroll
            for (int b = 0; b < B; b++)
                obase[(size_t)b * BSTRIDE + v] = __expf(x[b] * fac) * R[b];
        }
    }
}

extern "C" void kernel_launch(void* const* d_in, const int* in_sizes, int n_in,
                              void* d_out, int out_size) {
    const float* logits = (const float*)d_in[0];
    const int* prev = (const int*)d_in[1];
    float* out = (float*)d_out;
    (void)in_sizes; (void)n_in; (void)out_size;

    k_passA<<<S * NCHUNK, THREADS>>>(logits, prev);
    k_passC<<<S * NCHUNK, THREADS>>>(logits, prev, out);
}